// round 3
// baseline (speedup 1.0000x reference)
#include <cuda_runtime.h>
#include <cuda_bf16.h>
#include <cstdint>

// Scratch in static device memory. Layouts: [location][channel/k][batch], batch innermost.
__device__ float g_P0[400 * 54 * 4096];      // im2col of x
__device__ float g_H0[400 * 32 * 4096];      // layer0 out
__device__ float g_H1[100 * 64 * 4096];      // layer1 out
__device__ float g_H2[4 * 128 * 4096];       // layer2 out
__device__ float g_PART[8 * 4 * 128 * 4096]; // layer2 split-K partials [kz][loc][co][b]

static __device__ __forceinline__ float tanhap(float x) {
    float y; asm("tanh.approx.f32 %0, %1;" : "=f"(y) : "f"(x)); return y;
}
static __device__ __forceinline__ unsigned long long pack2(float w) {
    unsigned long long p; asm("mov.b64 %0, {%1, %1};" : "=l"(p) : "f"(w)); return p;
}
static __device__ __forceinline__ void ffma2(unsigned long long& acc,
                                             unsigned long long a, unsigned long long w2) {
    asm("fma.rn.f32x2 %0, %1, %2, %0;" : "+l"(acc) : "l"(a), "l"(w2));
}
static __device__ __forceinline__ void cpa16(void* s, const void* g) {
    uint32_t sa = (uint32_t)__cvta_generic_to_shared(s);
    asm volatile("cp.async.ca.shared.global [%0], [%1], 16;" :: "r"(sa), "l"(g));
}
static __device__ __forceinline__ void cpa_wait() {
    asm volatile("cp.async.commit_group;");
    asm volatile("cp.async.wait_group 0;");
}

// ---------------------------------------------------------------------------
// im2col: x[B,6,60,60] -> g_P0[loc][k][B]
// ---------------------------------------------------------------------------
__global__ void __launch_bounds__(256) im2col_k(const float* __restrict__ x) {
    const int ch = blockIdx.x;          // 0..359
    const int c = ch / 60, h = ch % 60;
    const int b0 = blockIdx.y * 32;
    __shared__ float s[32 * 61];
    const float* src = x + ((size_t)b0 * 6 + c) * 3600 + (size_t)h * 60;
    for (int e = threadIdx.x; e < 32 * 60; e += 256) {
        int bl = e / 60, w = e - bl * 60;
        s[bl * 61 + w] = src[(size_t)bl * 21600 + w];
    }
    __syncthreads();
    const int i = h / 3, dh = h % 3;
    for (int e = threadIdx.x; e < 32 * 60; e += 256) {
        int w = e >> 5, bl = e & 31;
        int j = w / 3, dw = w - j * 3;
        g_P0[((size_t)(i * 20 + j) * 54 + c * 9 + dh * 3 + dw) * 4096 + b0 + bl] =
            s[bl * 61 + w];
    }
}

// ---------------------------------------------------------------------------
// Locally-connected GEMM. 256 threads. Tile: BB batches x COUT_BLK couts.
// Weights staged in smem PRE-DUPLICATED ({w,w} per float2) -> broadcast LDS.64,
// no MOV-pack in the inner loop. Thread: lane = batch-pair, cgrp = cout group.
// Dynamic smem: [ KCHUNK*BB floats A | COUT_BLK*KCHUNK float2 Wdup ].
// ---------------------------------------------------------------------------
template <int CIN, int KH, int KW, int WIN, int WOUT, int COUT, int COUT_BLK,
          int KCHUNK, int BB, int KSPLIT, bool PARTIAL, int KZSTRIDE>
static __device__ __forceinline__ void lc_gemm_body(const float* __restrict__ in,
                                                    const float* __restrict__ W,
                                                    const float* __restrict__ bias,
                                                    float* __restrict__ out) {
    constexpr int K    = CIN * KH * KW;
    constexpr int KPER = K / KSPLIT;
    constexpr int NC   = COUT_BLK / 8;
    constexpr int NB2  = BB / 64;       // u64 batch-pairs per thread
    constexpr int B    = 4096;

    extern __shared__ __align__(16) float dsm[];
    float*  as  = dsm;                          // [KCHUNK][BB]
    float2* ws2 = (float2*)(dsm + KCHUNK * BB); // [COUT_BLK][KCHUNK] dup pairs

    const int loc = blockIdx.x;
    const int i = loc / WOUT, j = loc - i * WOUT;
    const int b0 = blockIdx.y * BB;
    const int cz = (blockIdx.z / KSPLIT) * COUT_BLK;
    const int kz = blockIdx.z % KSPLIT;
    const int t = threadIdx.x;
    const int lane = t & 31;
    const int cgrp = t >> 5;

    const float* Wl = W + ((size_t)loc * COUT + cz) * K;
    float* ob = out + (size_t)kz * KZSTRIDE;

    unsigned long long acc[NC][NB2];
#pragma unroll
    for (int c = 0; c < NC; c++) {
        unsigned long long p = PARTIAL ? 0ull
            : pack2(bias[(size_t)loc * COUT + cz + cgrp * NC + c]);
#pragma unroll
        for (int p2 = 0; p2 < NB2; p2++) acc[c][p2] = p;
    }

    const int kbeg = kz * KPER, kend = kbeg + KPER;
    for (int k0 = kbeg; k0 < kend; k0 += KCHUNK) {
        // A tile via cp.async (rows are contiguous, 16B-aligned: stride B=4096)
        for (int id = t; id < KCHUNK * BB / 4; id += 256) {
            int kc = id / (BB / 4), off = (id % (BB / 4)) * 4;
            int k = k0 + kc;
            int c = k / (KH * KW);
            int r = k - c * (KH * KW);
            int dh = r / KW, dw = r - dh * KW;
            int loc_in = (KH * i + dh) * WIN + KW * j + dw;
            cpa16(&as[kc * BB + off],
                  in + ((size_t)loc_in * CIN + c) * B + b0 + off);
        }
        // W tile, duplicated
        for (int id = t; id < COUT_BLK * KCHUNK; id += 256) {
            int co = id / KCHUNK, kc = id - co * KCHUNK;
            float w = __ldg(Wl + (size_t)co * K + k0 + kc);
            ws2[id] = make_float2(w, w);
        }
        cpa_wait();
        __syncthreads();

        const unsigned long long* a2 = (const unsigned long long*)as;
        const unsigned long long* w2p = (const unsigned long long*)ws2;
#pragma unroll 4
        for (int kc = 0; kc < KCHUNK; kc++) {
            unsigned long long a[NB2];
#pragma unroll
            for (int p = 0; p < NB2; p++) a[p] = a2[kc * (BB / 2) + p * 32 + lane];
#pragma unroll
            for (int c = 0; c < NC; c++) {
                unsigned long long w2 = w2p[(cgrp * NC + c) * KCHUNK + kc];
#pragma unroll
                for (int p = 0; p < NB2; p++) ffma2(acc[c][p], a[p], w2);
            }
        }
        __syncthreads();
    }

#pragma unroll
    for (int c = 0; c < NC; c++) {
        size_t obase = ((size_t)loc * COUT + cz + cgrp * NC + c) * B + b0;
#pragma unroll
        for (int p = 0; p < NB2; p++) {
            float x0, x1;
            asm("mov.b64 {%0, %1}, %2;" : "=f"(x0), "=f"(x1) : "l"(acc[c][p]));
            if (!PARTIAL) { x0 = tanhap(x0); x1 = tanhap(x1); }
            ((float2*)(ob + obase + p * 64))[lane] = make_float2(x0, x1);
        }
    }
}

// L0: CIN(eff K)=54, 1x1 "kernel" over g_P0. Tiles: 256b x 32co, KCHUNK=27.
__global__ void __launch_bounds__(256, 3) k_l0(const float* __restrict__ W,
                                               const float* __restrict__ b) {
    lc_gemm_body<54, 1, 1, 20, 20, 32, 32, 27, 256, 1, false, 0>(g_P0, W, b, g_H0);
}
// L1: 256b x 64co, KCHUNK=32 (K=128)
__global__ void __launch_bounds__(256, 2) k_l1(const float* __restrict__ W,
                                               const float* __restrict__ b) {
    lc_gemm_body<32, 2, 2, 20, 10, 64, 64, 32, 256, 1, false, 0>(g_H0, W, b, g_H1);
}
// L2: 256b x 64co, split-K=8 (KPER=200, KCHUNK=40), partials
__global__ void __launch_bounds__(256, 2) k_l2(const float* __restrict__ W,
                                               const float* __restrict__ b) {
    lc_gemm_body<64, 5, 5, 10, 2, 128, 64, 40, 256, 8, true, 4 * 128 * 4096>(
        g_H1, W, b, g_PART);
}

// Reduce 8 split-K partials + bias + tanh -> g_H2 (float4 per thread)
__global__ void __launch_bounds__(256) l2_combine_k(const float* __restrict__ B2) {
    constexpr int ST4 = 4 * 128 * 4096 / 4;
    int idx4 = blockIdx.x * 256 + threadIdx.x;    // over 2.1M/4
    int row = idx4 >> 10;                         // loc*128+co
    const float4* p = (const float4*)g_PART;
    float4 s = p[idx4];
#pragma unroll
    for (int z = 1; z < 8; z++) {
        float4 v = p[idx4 + z * ST4];
        s.x += v.x; s.y += v.y; s.z += v.z; s.w += v.w;
    }
    float bv = B2[row];
    float4 o = make_float4(tanhap(s.x + bv), tanhap(s.y + bv),
                           tanhap(s.z + bv), tanhap(s.w + bv));
    ((float4*)g_H2)[idx4] = o;
}

// ---------------------------------------------------------------------------
// Classifier + softmax. 128 blocks x 256 threads: 32 batches x 8 f-groups.
// ---------------------------------------------------------------------------
__global__ void __launch_bounds__(256) classifier_k(const float* __restrict__ info,
                                                    const float* __restrict__ Wc,
                                                    const float* __restrict__ bc,
                                                    float* __restrict__ out) {
    __shared__ float wsm[1030];
    __shared__ float red[8][32][2];
    for (int e = threadIdx.x; e < 1028; e += 256) wsm[e] = Wc[e];
    if (threadIdx.x < 2) wsm[1028 + threadIdx.x] = bc[threadIdx.x];
    __syncthreads();

    const int fg = threadIdx.x >> 5, lane = threadIdx.x & 31;
    const int b = blockIdx.x * 32 + lane;
    float l0 = 0.f, l1 = 0.f;
#pragma unroll 8
    for (int ff = 0; ff < 64; ff++) {
        int f = fg * 64 + ff;
        int row = (f & 3) * 128 + (f >> 2);
        float hv = g_H2[(size_t)row * 4096 + b];
        l0 += hv * wsm[f * 2];
        l1 += hv * wsm[f * 2 + 1];
    }
    red[fg][lane][0] = l0;
    red[fg][lane][1] = l1;
    __syncthreads();

    if (threadIdx.x < 32) {
        int bb = blockIdx.x * 32 + threadIdx.x;
        float s0 = wsm[1028], s1 = wsm[1029];
#pragma unroll
        for (int g = 0; g < 8; g++) { s0 += red[g][threadIdx.x][0]; s1 += red[g][threadIdx.x][1]; }
        float i0 = info[2 * bb], i1 = info[2 * bb + 1];
        s0 += i0 * wsm[512 * 2]     + i1 * wsm[513 * 2];
        s1 += i0 * wsm[512 * 2 + 1] + i1 * wsm[513 * 2 + 1];
        float m = fmaxf(s0, s1);
        float e0 = __expf(s0 - m), e1 = __expf(s1 - m);
        float inv = 1.0f / (e0 + e1);
        ((float2*)out)[bb] = make_float2(e0 * inv, e1 * inv);
    }
}

extern "C" void kernel_launch(void* const* d_in, const int* in_sizes, int n_in,
                              void* d_out, int out_size) {
    const float* x    = (const float*)d_in[0];
    const float* info = (const float*)d_in[1];
    const float* W0   = (const float*)d_in[2];
    const float* B0   = (const float*)d_in[3];
    const float* W1   = (const float*)d_in[4];
    const float* B1   = (const float*)d_in[5];
    const float* W2   = (const float*)d_in[6];
    const float* B2   = (const float*)d_in[7];
    const float* Wc   = (const float*)d_in[8];
    const float* bc   = (const float*)d_in[9];
    float* out = (float*)d_out;

    // Dynamic smem sizes: A tile + duplicated W tile
    const int s_l0 = (27 * 256) * 4 + (32 * 27) * 8;   // 27648 + 6912  = 34560
    const int s_l1 = (32 * 256) * 4 + (64 * 32) * 8;   // 32768 + 16384 = 49152
    const int s_l2 = (40 * 256) * 4 + (64 * 40) * 8;   // 40960 + 20480 = 61440
    cudaFuncSetAttribute(k_l0, cudaFuncAttributeMaxDynamicSharedMemorySize, s_l0);
    cudaFuncSetAttribute(k_l1, cudaFuncAttributeMaxDynamicSharedMemorySize, s_l1);
    cudaFuncSetAttribute(k_l2, cudaFuncAttributeMaxDynamicSharedMemorySize, s_l2);

    im2col_k<<<dim3(360, 128), 256>>>(x);
    k_l0<<<dim3(400, 16, 1), 256, s_l0>>>(W0, B0);     // 6400 blocks
    k_l1<<<dim3(100, 16, 1), 256, s_l1>>>(W1, B1);     // 1600 blocks
    k_l2<<<dim3(4, 16, 16), 256, s_l2>>>(W2, B2);      // 1024 blocks (2 cout x 8 ksplit)
    l2_combine_k<<<4 * 128 * 4096 / 4 / 256, 256>>>(B2);
    classifier_k<<<128, 256>>>(info, Wc, bc, out);
}